// round 14
// baseline (speedup 1.0000x reference)
#include <cuda_runtime.h>
#include <cuda_bf16.h>
#include <cuda_fp16.h>

#define F        128
#define F4       32          // F/4
#define FH2      64          // F/2 half2 per row
#define NMAX     100000
#define EMAX     1600000
#define BM       64          // rows per GEMM tile
#define NSM      148
#define SCAN_BLK 1024
#define NBMAX    ((NMAX + SCAN_BLK - 1) / SCAN_BLK)

// Scratch (allocation-free rule: device globals are the sanctioned path)
__device__ __half2 g_xh[NMAX * FH2];         // fp16 copy of x (25.6 MB)
__device__ __half2 g_aggh[NMAX * FH2];       // fp16 aggregate (pre-divided by deg)
__device__ int     g_cnt[NMAX];              // degree counters
__device__ int     g_rowptr[NMAX + 1];       // CSR row pointers
__device__ int     g_woff[NMAX];             // working offsets for bucket scatter
__device__ int     g_bsum[NBMAX];            // scan block sums
__device__ int2    g_epair[EMAX];            // CSR-ordered {col, val_bits}

// packed f32x2 helpers (Blackwell FFMA2)
__device__ __forceinline__ void fma2(unsigned long long& d,
                                     unsigned long long a,
                                     unsigned long long b) {
    asm("fma.rn.f32x2 %0, %1, %2, %0;" : "+l"(d) : "l"(a), "l"(b));
}
__device__ __forceinline__ unsigned long long pack2(float lo, float hi) {
    unsigned long long u;
    asm("mov.b64 %0, {%1, %2};" : "=l"(u) : "f"(lo), "f"(hi));
    return u;
}
__device__ __forceinline__ float2 unpack2(unsigned long long u) {
    float lo, hi;
    asm("mov.b64 {%0, %1}, %2;" : "=f"(lo), "=f"(hi) : "l"(u));
    return make_float2(lo, hi);
}

// ---------------------------------------------------------------------------
// Kernel A: one-time fp32 -> fp16 convert of x (streaming)
// ---------------------------------------------------------------------------
__global__ void tohalf_kernel(const float2* __restrict__ x2, int n_half2) {
    int i = blockIdx.x * blockDim.x + threadIdx.x;
    if (i < n_half2) g_xh[i] = __float22half2_rn(x2[i]);
}

// ---------------------------------------------------------------------------
// Kernel 0: zero the degree counters
// ---------------------------------------------------------------------------
__global__ void zero_cnt_kernel(int n_nodes) {
    int i = blockIdx.x * blockDim.x + threadIdx.x;
    if (i < n_nodes) g_cnt[i] = 0;
}

// ---------------------------------------------------------------------------
// Kernel 1: count degrees (2 edges/thread)
// ---------------------------------------------------------------------------
__global__ void count_kernel(const int* __restrict__ row, int E) {
    int e = (blockIdx.x * blockDim.x + threadIdx.x) * 2;
    if (e + 1 < E) {
        int2 r2 = *(const int2*)&row[e];
        atomicAdd(&g_cnt[r2.x], 1);
        atomicAdd(&g_cnt[r2.y], 1);
    } else if (e < E) {
        atomicAdd(&g_cnt[row[e]], 1);
    }
}

// ---------------------------------------------------------------------------
// Kernels 2-4: exclusive scan of degrees -> row_ptr (3-stage)
// ---------------------------------------------------------------------------
__global__ void scan1_kernel(int n_nodes) {
    __shared__ int sh[SCAN_BLK];
    int gi = blockIdx.x * SCAN_BLK + threadIdx.x;
    int v  = (gi < n_nodes) ? g_cnt[gi] : 0;
    sh[threadIdx.x] = v;
    __syncthreads();
#pragma unroll
    for (int off = 1; off < SCAN_BLK; off <<= 1) {
        int t = (threadIdx.x >= off) ? sh[threadIdx.x - off] : 0;
        __syncthreads();
        sh[threadIdx.x] += t;
        __syncthreads();
    }
    if (gi < n_nodes) g_cnt[gi] = sh[threadIdx.x] - v;       // exclusive within block
    if (threadIdx.x == SCAN_BLK - 1) g_bsum[blockIdx.x] = sh[threadIdx.x];
}

__global__ void scan2_kernel(int nb) {                        // one block, nb <= 1024
    __shared__ int sh[SCAN_BLK];
    int v = (threadIdx.x < nb) ? g_bsum[threadIdx.x] : 0;
    sh[threadIdx.x] = v;
    __syncthreads();
#pragma unroll
    for (int off = 1; off < SCAN_BLK; off <<= 1) {
        int t = (threadIdx.x >= off) ? sh[threadIdx.x - off] : 0;
        __syncthreads();
        sh[threadIdx.x] += t;
        __syncthreads();
    }
    if (threadIdx.x < nb) g_bsum[threadIdx.x] = sh[threadIdx.x] - v;  // exclusive
}

__global__ void scan3_kernel(int n_nodes, int E) {
    int gi = blockIdx.x * SCAN_BLK + threadIdx.x;
    if (gi < n_nodes) {
        int r = g_cnt[gi] + g_bsum[blockIdx.x];
        g_rowptr[gi] = r;
        g_woff[gi]   = r;
    }
    if (gi == 0) g_rowptr[n_nodes] = E;
}

// ---------------------------------------------------------------------------
// Kernel 5: bucket-permute {col, val} into CSR order (2 edges/thread)
// ---------------------------------------------------------------------------
__global__ void bucket_kernel(const int*   __restrict__ row,
                              const int*   __restrict__ col,
                              const float* __restrict__ val,
                              int E) {
    int e = (blockIdx.x * blockDim.x + threadIdx.x) * 2;
    if (e + 1 < E) {
        int2   r2 = *(const int2*)&row[e];
        int2   c2 = *(const int2*)&col[e];
        float2 v2 = *(const float2*)&val[e];
        int p0 = atomicAdd(&g_woff[r2.x], 1);
        g_epair[p0] = make_int2(c2.x, __float_as_int(v2.x));
        int p1 = atomicAdd(&g_woff[r2.y], 1);
        g_epair[p1] = make_int2(c2.y, __float_as_int(v2.y));
    } else if (e < E) {
        int pos = atomicAdd(&g_woff[row[e]], 1);
        g_epair[pos] = make_int2(col[e], __float_as_int(val[e]));
    }
}

// ---------------------------------------------------------------------------
// Kernel 6: warp-per-node gather aggregate over fp16 x (256B/edge instead of
//   512B), fp32 accumulation, fp16 output. 2-way unrolled (MLP=2).
// ---------------------------------------------------------------------------
__global__ void aggregate_kernel(int n_nodes) {
    int nid  = (blockIdx.x * blockDim.x + threadIdx.x) >> 5;
    int lane = threadIdx.x & 31;
    if (nid >= n_nodes) return;

    int s    = g_rowptr[nid];
    int tEnd = g_rowptr[nid + 1];

    float4 a0 = make_float4(0.f, 0.f, 0.f, 0.f);
    float4 a1 = make_float4(0.f, 0.f, 0.f, 0.f);

    for (int base = s; base < tEnd; base += 32) {
        int e = base + lane;
        int2 p = (e < tEnd) ? g_epair[e] : make_int2(0, 0);
        int cnt = min(32, tEnd - base);
        int j = 0;
        for (; j + 2 <= cnt; j += 2) {
            int   c0 = __shfl_sync(0xffffffffu, p.x, j);
            float v0 = __int_as_float(__shfl_sync(0xffffffffu, p.y, j));
            int   c1 = __shfl_sync(0xffffffffu, p.x, j + 1);
            float v1 = __int_as_float(__shfl_sync(0xffffffffu, p.y, j + 1));
            uint2 r0 = *(const uint2*)&g_xh[(long long)c0 * FH2 + lane * 2];
            uint2 r1 = *(const uint2*)&g_xh[(long long)c1 * FH2 + lane * 2];
            float2 f0a = __half22float2(*(const __half2*)&r0.x);
            float2 f0b = __half22float2(*(const __half2*)&r0.y);
            float2 f1a = __half22float2(*(const __half2*)&r1.x);
            float2 f1b = __half22float2(*(const __half2*)&r1.y);
            a0.x += v0 * f0a.x; a0.y += v0 * f0a.y;
            a0.z += v0 * f0b.x; a0.w += v0 * f0b.y;
            a1.x += v1 * f1a.x; a1.y += v1 * f1a.y;
            a1.z += v1 * f1b.x; a1.w += v1 * f1b.y;
        }
        if (j < cnt) {
            int   c0 = __shfl_sync(0xffffffffu, p.x, j);
            float v0 = __int_as_float(__shfl_sync(0xffffffffu, p.y, j));
            uint2 r0 = *(const uint2*)&g_xh[(long long)c0 * FH2 + lane * 2];
            float2 f0a = __half22float2(*(const __half2*)&r0.x);
            float2 f0b = __half22float2(*(const __half2*)&r0.y);
            a0.x += v0 * f0a.x; a0.y += v0 * f0a.y;
            a0.z += v0 * f0b.x; a0.w += v0 * f0b.y;
        }
    }
    float inv = 1.f / fmaxf((float)(tEnd - s), 1.f);
    __half2 h0 = __floats2half2_rn((a0.x + a1.x) * inv, (a0.y + a1.y) * inv);
    __half2 h1 = __floats2half2_rn((a0.z + a1.z) * inv, (a0.w + a1.w) * inv);
    uint2 outw;
    outw.x = *(const unsigned int*)&h0;
    outw.y = *(const unsigned int*)&h1;
    *(uint2*)&g_aggh[(long long)nid * FH2 + lane * 2] = outw;
}

// ---------------------------------------------------------------------------
// Kernel 7: PERSISTENT fused  out = relu( agg @ Wl^T + b + x @ Wr^T )
//   [R7-champion structure; agg prefetch now reads fp16 and widens to fp32]
// ---------------------------------------------------------------------------
__global__ __launch_bounds__(256, 1)
void gemm_kernel(const float4* __restrict__ x4,
                 const float*  __restrict__ Wl,
                 const float*  __restrict__ Wr,
                 const float*  __restrict__ bl,
                 float*        __restrict__ out,
                 int n_nodes, int ntiles) {
    extern __shared__ float2 sm2[];
    float2* wpair = sm2;               // [k][j] {wl, wr}  128*128
    float2* axs   = wpair + F * F;     // [r][k] {agg, x}   64*128

    const int t = threadIdx.x;

    // W fill once: consecutive threads -> consecutive j => conflict-free STS.
    for (int i = t; i < F * F; i += 256) {
        int j = i & 127;
        int k = i >> 7;
        wpair[k * F + j] = make_float2(Wl[j * F + k], Wr[j * F + k]);
    }

    const int wid  = t >> 5;
    const int lane = t & 31;
    const int i0   = wid * 8;
    const int j0   = lane * 4;
    const float4 bv = *(const float4*)&bl[j0];

    // register staging for one tile: 8 (agg,x) float4 pairs per thread
    float4 pa[8], px[8];

    auto load_agg4 = [](long long gi, int c4) -> float4 {
        uint2 r = *(const uint2*)&g_aggh[gi * FH2 + c4 * 2];
        float2 a = __half22float2(*(const __half2*)&r.x);
        float2 b = __half22float2(*(const __half2*)&r.y);
        return make_float4(a.x, a.y, b.x, b.y);
    };

    // prefetch first tile
    {
        int tile = blockIdx.x;
#pragma unroll
        for (int u = 0; u < 8; u++) {
            int idx = t + u * 256;               // < 2048 = BM*F4
            int gi  = tile * BM + (idx >> 5);
            int c4  = idx & 31;
            bool ok = (tile < ntiles) && (gi < n_nodes);
            pa[u] = ok ? load_agg4(gi, c4) : make_float4(0.f, 0.f, 0.f, 0.f);
            px[u] = ok ? x4[(long long)gi * F4 + c4]
                       : make_float4(0.f, 0.f, 0.f, 0.f);
        }
    }

    for (int tile = blockIdx.x; tile < ntiles; tile += gridDim.x) {
        __syncthreads();          // axs free (prev tile's readers done); W ready
        // STS staged tile
#pragma unroll
        for (int u = 0; u < 8; u++) {
            int idx = t + u * 256;
            int r   = idx >> 5;
            int c4  = idx & 31;
            float2* dst = &axs[r * F + c4 * 4];
            dst[0] = make_float2(pa[u].x, px[u].x);
            dst[1] = make_float2(pa[u].y, px[u].y);
            dst[2] = make_float2(pa[u].z, px[u].z);
            dst[3] = make_float2(pa[u].w, px[u].w);
        }
        __syncthreads();

        // prefetch NEXT tile (LDGs overlap with compute below)
        {
            int nt = tile + gridDim.x;
#pragma unroll
            for (int u = 0; u < 8; u++) {
                int idx = t + u * 256;
                int gi  = nt * BM + (idx >> 5);
                int c4  = idx & 31;
                bool ok = (nt < ntiles) && (gi < n_nodes);
                pa[u] = ok ? load_agg4(gi, c4) : make_float4(0.f, 0.f, 0.f, 0.f);
                px[u] = ok ? x4[(long long)gi * F4 + c4]
                           : make_float4(0.f, 0.f, 0.f, 0.f);
            }
        }

        // compute 64x128 tile
        unsigned long long acc[8][4];
#pragma unroll
        for (int r = 0; r < 8; r++) {
            acc[r][0] = pack2(bv.x, 0.f);
            acc[r][1] = pack2(bv.y, 0.f);
            acc[r][2] = pack2(bv.z, 0.f);
            acc[r][3] = pack2(bv.w, 0.f);
        }

#pragma unroll 4
        for (int k = 0; k < F; k++) {
            ulonglong2 wa = *(const ulonglong2*)&wpair[k * F + j0];
            ulonglong2 wb = *(const ulonglong2*)&wpair[k * F + j0 + 2];
#pragma unroll
            for (int r = 0; r < 8; r++) {
                unsigned long long ax =
                    *(const unsigned long long*)&axs[(i0 + r) * F + k];
                fma2(acc[r][0], ax, wa.x);
                fma2(acc[r][1], ax, wa.y);
                fma2(acc[r][2], ax, wb.x);
                fma2(acc[r][3], ax, wb.y);
            }
        }

        int row0 = tile * BM;
#pragma unroll
        for (int r = 0; r < 8; r++) {
            int gi = row0 + i0 + r;
            if (gi < n_nodes) {
                float2 c0 = unpack2(acc[r][0]);
                float2 c1 = unpack2(acc[r][1]);
                float2 c2 = unpack2(acc[r][2]);
                float2 c3 = unpack2(acc[r][3]);
                float4 o;
                o.x = fmaxf(c0.x + c0.y, 0.f);
                o.y = fmaxf(c1.x + c1.y, 0.f);
                o.z = fmaxf(c2.x + c2.y, 0.f);
                o.w = fmaxf(c3.x + c3.y, 0.f);
                *(float4*)&out[(long long)gi * F + j0] = o;
            }
        }
    }
}

// ---------------------------------------------------------------------------
// Launch
// ---------------------------------------------------------------------------
extern "C" void kernel_launch(void* const* d_in, const int* in_sizes, int n_in,
                              void* d_out, int out_size) {
    const float* x   = (const float*)d_in[0];
    const float* val = (const float*)d_in[1];
    const float* Wl  = (const float*)d_in[2];
    const float* bl  = (const float*)d_in[3];
    const float* Wr  = (const float*)d_in[4];
    const int*   row = (const int*)d_in[5];
    const int*   col = (const int*)d_in[6];
    float*       out = (float*)d_out;

    const int n_nodes = in_sizes[0] / F;
    const int E       = in_sizes[1];
    const int nb      = (n_nodes + SCAN_BLK - 1) / SCAN_BLK;
    const int epairs  = (E + 1) / 2;
    const int nh2     = n_nodes * FH2;

    // fp16 copy of x
    tohalf_kernel<<<(nh2 + 255) / 256, 256>>>((const float2*)x, nh2);

    // CSR build
    zero_cnt_kernel<<<(n_nodes + 255) / 256, 256>>>(n_nodes);
    count_kernel<<<(epairs + 511) / 512, 512>>>(row, E);
    scan1_kernel<<<nb, SCAN_BLK>>>(n_nodes);
    scan2_kernel<<<1, SCAN_BLK>>>(nb);
    scan3_kernel<<<nb, SCAN_BLK>>>(n_nodes, E);
    bucket_kernel<<<(epairs + 511) / 512, 512>>>(row, col, val, E);

    // gather-side aggregation over fp16 x (warp per node)
    aggregate_kernel<<<(n_nodes * 32 + 255) / 256, 256>>>(n_nodes);

    // persistent fused GEMM + bias + relu (packed f32x2)
    static const size_t smem_bytes = (size_t)(F * F + BM * F) * sizeof(float2);
    cudaFuncSetAttribute(gemm_kernel, cudaFuncAttributeMaxDynamicSharedMemorySize,
                         (int)smem_bytes);
    int ntiles = (n_nodes + BM - 1) / BM;
    gemm_kernel<<<NSM, 256, smem_bytes>>>((const float4*)x, Wl, Wr, bl, out,
                                          n_nodes, ntiles);
}